// round 10
// baseline (speedup 1.0000x reference)
#include <cuda_runtime.h>
#include <cuda_bf16.h>

// Problem constants (fixed by the reference)
#define WF 512.0f
#define HF 512.0f
#define NGMAX 2048
#define TILES_X 16
#define TILES_Y 16
#define TILES (TILES_X * TILES_Y)
#define TILE_W 32.0f
#define PCAP 1024             // per-tile pixel list capacity (mean 256)
#define NSEG 8                // warp-segments per block
#define SEG 256               // gaussians per segment (2048/8)
#define SEGCAP 96             // staged coefficients per segment (overflow -> global)
#define TPB 256
#define NBLOCKS 256           // == TILES; also == B/TPB for binning

// Per-gaussian packed coefficients: 2 x float4: [P,Q,R,mx] [my,cr,cg,cb]
// (P,Q,R pre-scaled by -log2(e) so exp is a single ex2)
__device__ float4 g_coef[NGMAX * 2];
__device__ float4 g_cull[NGMAX];          // [mx, my, r2, 0]
__device__ int g_pcnt[TILES];             // statically zero; re-zeroed in-kernel
__device__ int g_pidx[TILES * PCAP];
__device__ float2 g_pxy[TILES * PCAP];
__device__ unsigned g_bar;                // monotonic grid-barrier counter

__device__ __forceinline__ float ex2(float x) {
    float r; asm("ex2.approx.ftz.f32 %0,%1;" : "=f"(r) : "f"(x)); return r;
}
__device__ __forceinline__ float rcp(float x) {
    float r; asm("rcp.approx.ftz.f32 %0,%1;" : "=f"(r) : "f"(x)); return r;
}
__device__ __forceinline__ float fexp(float x) { return ex2(x * 1.4426950408889634f); }
__device__ __forceinline__ float ftanh(float x) {
    float e = ex2(x * 2.8853900817779268f);   // e^{2x}
    return 1.0f - 2.0f * rcp(e + 1.0f);
}
__device__ __forceinline__ float fsigm(float x) {
    return rcp(1.0f + fexp(-x));
}

// Grid-wide barrier, graph-replay safe (monotonic counter, no reset needed).
// Requires all blocks co-resident (grid=256 <= 2 blocks/SM * 148 SMs).
__device__ __forceinline__ void grid_barrier() {
    __syncthreads();
    if (threadIdx.x == 0) {
        __threadfence();                                  // publish phase-A writes
        unsigned old = atomicAdd(&g_bar, 1u);
        unsigned target = old - (old % (unsigned)gridDim.x) + (unsigned)gridDim.x;
        unsigned cur;
        do {
            asm volatile("ld.acquire.gpu.global.u32 %0, [%1];"
                         : "=r"(cur) : "l"(&g_bar));
        } while (cur < target);
        __threadfence();
    }
    __syncthreads();
}

// ---------------------------------------------------------------------------
// Single fused kernel. grid = 256 x 256 (all blocks co-resident).
// Phase A: coefficients (threads with gtid < N) + pixel binning (1 px/thread).
// Grid barrier.
// Phase B: block t = tile t. 8 warps ballot-compact their 256-gaussian
// segments into smem (index order preserved -> deterministic accumulation),
// then each thread splats its tile pixels over segments 0..7 in order.
// ---------------------------------------------------------------------------
__global__ void __launch_bounds__(TPB, 2)
fused_splat(const float* __restrict__ x,
            const float* __restrict__ rgb,
            const float* __restrict__ mu,
            const float* __restrict__ scale,
            const float* __restrict__ angle,
            float* __restrict__ out,
            int N, int B) {
    __shared__ float4 scoef[NSEG][SEGCAP][2];     // 24 KB
    __shared__ unsigned short slist[NSEG][SEG];   // 4 KB (overflow path)
    __shared__ int scnt[NSEG];
    __shared__ int s_pcnt;

    const int tid = threadIdx.x;
    const int gtid = blockIdx.x * TPB + tid;

    // ================= Phase A =================
    if (gtid < N) {
        const float MU_BORDER = 1.05f;
        const float PI_APPROX = 3.1416f;
        const float S_MIN = 1.0f / 30.0f;
        const float S_MAX = 1.0f / 0.75f;
        const float LOG2E = 1.4426950408889634f;
        int i = gtid;

        float mpx = (ftanh(mu[2 * i + 0]) * MU_BORDER + 1.0f) * 0.5f * WF;
        float mpy = (ftanh(mu[2 * i + 1]) * MU_BORDER + 1.0f) * 0.5f * HF;

        float al = ftanh(angle[i]) * PI_APPROX;
        float c, s;
        __sincosf(al, &s, &c);

        float S0 = fsigm(scale[2 * i + 0]) * (S_MAX - S_MIN) + S_MIN;
        float S1 = fsigm(scale[2 * i + 1]) * (S_MAX - S_MIN) + S_MIN;

        float a = S0 * c, b = -S0 * s;
        float e = S1 * s, f = S1 * c;

        float P = -LOG2E * (a * a + e * e);
        float Q = -LOG2E * 2.0f * (a * b + e * f);
        float R = -LOG2E * (b * b + f * f);

        float cr = fsigm(rgb[3 * i + 0]);
        float cg = fsigm(rgb[3 * i + 1]);
        float cb = fsigm(rgb[3 * i + 2]);

        float Smin = fminf(S0, S1);
        float r = 5.0f / Smin;                  // w = e^-25 level set
        float r2 = r * r * 1.0001f + 1e-2f;

        g_coef[2 * i]     = make_float4(P, Q, R, mpx);
        g_coef[2 * i + 1] = make_float4(mpy, cr, cg, cb);
        g_cull[i]         = make_float4(mpx, mpy, r2, 0.0f);
    }

    // pixel binning: exactly 1 pixel per thread (grid*TPB == B)
    if (gtid < B) {
        float2 xy = ((const float2*)x)[gtid];
        int tx = (int)(xy.x * (1.0f / TILE_W));
        int ty = (int)(xy.y * (1.0f / TILE_W));
        tx = min(max(tx, 0), TILES_X - 1);
        ty = min(max(ty, 0), TILES_Y - 1);
        int t = ty * TILES_X + tx;
        int slot = atomicAdd(&g_pcnt[t], 1);
        if (slot < PCAP) {
            g_pidx[t * PCAP + slot] = gtid;
            g_pxy[t * PCAP + slot] = xy;
        }
    }

    // ================= barrier =================
    grid_barrier();

    // ================= Phase B =================
    const int t = blockIdx.x;          // tile
    const int w = tid >> 5;
    const int lane = tid & 31;

    // read this tile's pixel count, then re-zero for the next launch
    if (tid == 0) {
        s_pcnt = min(g_pcnt[t], PCAP);
        g_pcnt[t] = 0;
    }

    const float tx0 = (float)(t & (TILES_X - 1)) * TILE_W;
    const float ty0 = (float)(t >> 4) * TILE_W;
    const float tx1 = tx0 + TILE_W;
    const float ty1 = ty0 + TILE_W;

    // cull scan + coefficient staging: warp w covers [w*SEG, (w+1)*SEG)
    {
        int cnt = 0;
        for (int c0 = w * SEG; c0 < (w + 1) * SEG; c0 += 32) {
            int gi = c0 + lane;
            float4 cu = g_cull[gi];
            float dx = fmaxf(fmaxf(tx0 - cu.x, cu.x - tx1), 0.0f);
            float dy = fmaxf(fmaxf(ty0 - cu.y, cu.y - ty1), 0.0f);
            bool ok = (dx * dx + dy * dy) <= cu.z;
            unsigned m = __ballot_sync(0xffffffffu, ok);
            if (ok) {
                int pos = cnt + __popc(m & ((1u << lane) - 1u));
                slist[w][pos] = (unsigned short)gi;
                if (pos < SEGCAP) {
                    scoef[w][pos][0] = g_coef[2 * gi];
                    scoef[w][pos][1] = g_coef[2 * gi + 1];
                }
            }
            cnt += __popc(m);
        }
        if (lane == 0) scnt[w] = cnt;
    }
    __syncthreads();

    const int pcnt = s_pcnt;

    for (int i = tid; i < pcnt; i += TPB) {
        float2 xy = g_pxy[t * PCAP + i];
        float px = xy.x, py = xy.y;

        float ar = 0.f, ag = 0.f, ab = 0.f;

#pragma unroll
        for (int seg = 0; seg < NSEG; seg++) {
            int n = scnt[seg];
            int nc = min(n, SEGCAP);
#pragma unroll 4
            for (int j = 0; j < nc; j++) {
                float4 cA = scoef[seg][j][0];     // P,Q,R,mx
                float4 cB = scoef[seg][j][1];     // my,cr,cg,cb
                float vx = px - cA.w;
                float vy = py - cB.x;
                float q = fmaf(vx, fmaf(cA.y, vy, cA.x * vx), (cA.z * vy) * vy);
                float wgt = ex2(q);
                ar = fmaf(wgt, cB.y, ar);
                ag = fmaf(wgt, cB.z, ag);
                ab = fmaf(wgt, cB.w, ab);
            }
            // overflow path (statistically never; preserves correctness)
            for (int j = SEGCAP; j < n; j++) {
                int gi = slist[seg][j];
                float4 cA = g_coef[2 * gi];
                float4 cB = g_coef[2 * gi + 1];
                float vx = px - cA.w;
                float vy = py - cB.x;
                float q = fmaf(vx, fmaf(cA.y, vy, cA.x * vx), (cA.z * vy) * vy);
                float wgt = ex2(q);
                ar = fmaf(wgt, cB.y, ar);
                ag = fmaf(wgt, cB.z, ag);
                ab = fmaf(wgt, cB.w, ab);
            }
        }

        int pix = g_pidx[t * PCAP + i];
        out[3 * pix + 0] = ar;
        out[3 * pix + 1] = ag;
        out[3 * pix + 2] = ab;
    }
}

// ---------------------------------------------------------------------------
// Launch: inputs in metadata order: x[B,2], rgb[N,3], mu[N,2], scale[N,2], angle[N]
// ---------------------------------------------------------------------------
extern "C" void kernel_launch(void* const* d_in, const int* in_sizes, int n_in,
                              void* d_out, int out_size) {
    const float* x     = (const float*)d_in[0];
    const float* rgb   = (const float*)d_in[1];
    const float* mu    = (const float*)d_in[2];
    const float* scale = (const float*)d_in[3];
    const float* angle = (const float*)d_in[4];
    float* out = (float*)d_out;

    int N = in_sizes[4];          // 2048
    int B = in_sizes[0] / 2;      // 65536

    fused_splat<<<NBLOCKS, TPB>>>(x, rgb, mu, scale, angle, out, N, B);
}

// round 11
// speedup vs baseline: 1.1748x; 1.1748x over previous
#include <cuda_runtime.h>
#include <cuda_bf16.h>

// Problem constants (fixed by the reference)
#define WF 512.0f
#define HF 512.0f
#define NGMAX 2048
#define TILES_X 16
#define TILES_Y 16
#define TILES (TILES_X * TILES_Y)
#define TILE_W 32.0f
#define PCAP 1024             // per-tile pixel list capacity (mean 256, max ~350)
#define NSEG 8                // warp-segments per splat block
#define SEG 256               // gaussians per segment (2048/8)
#define NCHUNK (SEG / 32)     // 8 batched cull chunks per warp
#define SEGCAP 64             // staged coefficients per segment (overflow -> global)
#define TPB 256

// Per-gaussian packed coefficients: 2 x float4: [P,Q,R,mx] [my,cr,cg,cb]
// (P,Q,R pre-scaled by -log2(e) so exp is a single ex2)
__device__ float4 g_coef[NGMAX * 2];
__device__ float4 g_cull[NGMAX];          // [mx, my, r2, 0]
__device__ int g_pcnt[TILES];             // statically zero; re-zeroed by splat
__device__ int g_pidx[TILES * PCAP];
__device__ float2 g_pxy[TILES * PCAP];

__device__ __forceinline__ float ex2(float x) {
    float r; asm("ex2.approx.ftz.f32 %0,%1;" : "=f"(r) : "f"(x)); return r;
}
__device__ __forceinline__ float rcp(float x) {
    float r; asm("rcp.approx.ftz.f32 %0,%1;" : "=f"(r) : "f"(x)); return r;
}
__device__ __forceinline__ float fexp(float x) { return ex2(x * 1.4426950408889634f); }
__device__ __forceinline__ float ftanh(float x) {
    float e = ex2(x * 2.8853900817779268f);   // e^{2x}
    return 1.0f - 2.0f * rcp(e + 1.0f);
}
__device__ __forceinline__ float fsigm(float x) {
    return rcp(1.0f + fexp(-x));
}

// ---------------------------------------------------------------------------
// Kernel 1: coefficients (gtid < N) + pixel binning (1 px/thread).
// g_pcnt starts zero (static init / re-zeroed by splat each replay).
// Cull: |d|^2 >= min(S0,S1)^2 |v|^2  =>  |v| > 5/minS gives w < e^-25.
// ---------------------------------------------------------------------------
__global__ void __launch_bounds__(TPB) prep_kernel(const float* __restrict__ rgb,
                                                   const float* __restrict__ mu,
                                                   const float* __restrict__ scale,
                                                   const float* __restrict__ angle,
                                                   const float* __restrict__ x,
                                                   int N, int B) {
    int gtid = blockIdx.x * TPB + threadIdx.x;

    if (gtid < N) {
        const float MU_BORDER = 1.05f;
        const float PI_APPROX = 3.1416f;
        const float S_MIN = 1.0f / 30.0f;
        const float S_MAX = 1.0f / 0.75f;
        const float LOG2E = 1.4426950408889634f;
        int i = gtid;

        float mpx = (ftanh(mu[2 * i + 0]) * MU_BORDER + 1.0f) * 0.5f * WF;
        float mpy = (ftanh(mu[2 * i + 1]) * MU_BORDER + 1.0f) * 0.5f * HF;

        float al = ftanh(angle[i]) * PI_APPROX;
        float c, s;
        __sincosf(al, &s, &c);

        float S0 = fsigm(scale[2 * i + 0]) * (S_MAX - S_MIN) + S_MIN;
        float S1 = fsigm(scale[2 * i + 1]) * (S_MAX - S_MIN) + S_MIN;

        float a = S0 * c, b = -S0 * s;
        float e = S1 * s, f = S1 * c;

        float P = -LOG2E * (a * a + e * e);
        float Q = -LOG2E * 2.0f * (a * b + e * f);
        float R = -LOG2E * (b * b + f * f);

        float cr = fsigm(rgb[3 * i + 0]);
        float cg = fsigm(rgb[3 * i + 1]);
        float cb = fsigm(rgb[3 * i + 2]);

        float Smin = fminf(S0, S1);
        float r = 5.0f / Smin;                  // w = e^-25 level set
        float r2 = r * r * 1.0001f + 1e-2f;

        g_coef[2 * i]     = make_float4(P, Q, R, mpx);
        g_coef[2 * i + 1] = make_float4(mpy, cr, cg, cb);
        g_cull[i]         = make_float4(mpx, mpy, r2, 0.0f);
    }

    // pixel binning: exactly 1 pixel per thread (grid*TPB == B)
    if (gtid < B) {
        float2 xy = ((const float2*)x)[gtid];
        int tx = (int)(xy.x * (1.0f / TILE_W));
        int ty = (int)(xy.y * (1.0f / TILE_W));
        tx = min(max(tx, 0), TILES_X - 1);
        ty = min(max(ty, 0), TILES_Y - 1);
        int t = ty * TILES_X + tx;
        int slot = atomicAdd(&g_pcnt[t], 1);
        if (slot < PCAP) {
            g_pidx[t * PCAP + slot] = gtid;
            g_pxy[t * PCAP + slot] = xy;
        }
    }
}

// ---------------------------------------------------------------------------
// Kernel 2: per-tile splat, 1 block per tile (256 blocks x 256 threads).
// Cull scan: each warp BATCH-LOADS its 8 cull chunks (MLP=8, one latency
// exposure), then 8 ALU-only ballot rounds compact indices in order and
// stage the coefficients into smem. Pixel loop then runs pure LDS+FMA+ex2.
// Segments processed 0..7 in index order -> deterministic accumulation.
// Re-zeroes g_pcnt[t] for the next graph replay.
// ---------------------------------------------------------------------------
__global__ void __launch_bounds__(TPB) splat_tiled(float* __restrict__ out) {
    __shared__ float4 scoef[NSEG][SEGCAP][2];     // 16 KB
    __shared__ unsigned short slist[NSEG][SEG];   // 4 KB (overflow path)
    __shared__ int scnt[NSEG];
    __shared__ int s_pcnt;

    const int t = blockIdx.x;
    const int tid = threadIdx.x;
    const int w = tid >> 5;
    const int lane = tid & 31;

    if (tid == 0) {
        s_pcnt = min(g_pcnt[t], PCAP);
        g_pcnt[t] = 0;                       // reset for next replay
    }

    const float tx0 = (float)(t & (TILES_X - 1)) * TILE_W;
    const float ty0 = (float)(t >> 4) * TILE_W;
    const float tx1 = tx0 + TILE_W;
    const float ty1 = ty0 + TILE_W;

    // ---- batched cull scan: warp w covers [w*SEG, (w+1)*SEG) ----
    {
        float4 cu[NCHUNK];
#pragma unroll
        for (int c = 0; c < NCHUNK; c++)
            cu[c] = g_cull[w * SEG + c * 32 + lane];    // 8 independent LDG.128

        int cnt = 0;
#pragma unroll
        for (int c = 0; c < NCHUNK; c++) {
            int gi = w * SEG + c * 32 + lane;
            float dx = fmaxf(fmaxf(tx0 - cu[c].x, cu[c].x - tx1), 0.0f);
            float dy = fmaxf(fmaxf(ty0 - cu[c].y, cu[c].y - ty1), 0.0f);
            bool ok = (dx * dx + dy * dy) <= cu[c].z;
            unsigned m = __ballot_sync(0xffffffffu, ok);
            if (ok) {
                int pos = cnt + __popc(m & ((1u << lane) - 1u));
                slist[w][pos] = (unsigned short)gi;
                if (pos < SEGCAP) {
                    scoef[w][pos][0] = g_coef[2 * gi];
                    scoef[w][pos][1] = g_coef[2 * gi + 1];
                }
            }
            cnt += __popc(m);
        }
        if (lane == 0) scnt[w] = cnt;
    }
    __syncthreads();

    const int pcnt = s_pcnt;

    // ---- pixel loop: ~1 px/thread, staged coefficients from smem ----
    for (int i = tid; i < pcnt; i += TPB) {
        float2 xy = g_pxy[t * PCAP + i];
        float px = xy.x, py = xy.y;

        float ar = 0.f, ag = 0.f, ab = 0.f;

#pragma unroll
        for (int seg = 0; seg < NSEG; seg++) {
            int n = scnt[seg];
            int nc = min(n, SEGCAP);
#pragma unroll 4
            for (int j = 0; j < nc; j++) {
                float4 cA = scoef[seg][j][0];     // P,Q,R,mx
                float4 cB = scoef[seg][j][1];     // my,cr,cg,cb
                float vx = px - cA.w;
                float vy = py - cB.x;
                float q = fmaf(vx, fmaf(cA.y, vy, cA.x * vx), (cA.z * vy) * vy);
                float wgt = ex2(q);
                ar = fmaf(wgt, cB.y, ar);
                ag = fmaf(wgt, cB.z, ag);
                ab = fmaf(wgt, cB.w, ab);
            }
            // overflow path (statistically never; preserves correctness)
            for (int j = SEGCAP; j < n; j++) {
                int gi = slist[seg][j];
                float4 cA = g_coef[2 * gi];
                float4 cB = g_coef[2 * gi + 1];
                float vx = px - cA.w;
                float vy = py - cB.x;
                float q = fmaf(vx, fmaf(cA.y, vy, cA.x * vx), (cA.z * vy) * vy);
                float wgt = ex2(q);
                ar = fmaf(wgt, cB.y, ar);
                ag = fmaf(wgt, cB.z, ag);
                ab = fmaf(wgt, cB.w, ab);
            }
        }

        int pix = g_pidx[t * PCAP + i];
        out[3 * pix + 0] = ar;
        out[3 * pix + 1] = ag;
        out[3 * pix + 2] = ab;
    }
}

// ---------------------------------------------------------------------------
// Launch: inputs in metadata order: x[B,2], rgb[N,3], mu[N,2], scale[N,2], angle[N]
// ---------------------------------------------------------------------------
extern "C" void kernel_launch(void* const* d_in, const int* in_sizes, int n_in,
                              void* d_out, int out_size) {
    const float* x     = (const float*)d_in[0];
    const float* rgb   = (const float*)d_in[1];
    const float* mu    = (const float*)d_in[2];
    const float* scale = (const float*)d_in[3];
    const float* angle = (const float*)d_in[4];
    float* out = (float*)d_out;

    int N = in_sizes[4];          // 2048
    int B = in_sizes[0] / 2;      // 65536

    prep_kernel<<<B / TPB, TPB>>>(rgb, mu, scale, angle, x, N, B);   // 256 blocks
    splat_tiled<<<TILES, TPB>>>(out);                                // 256 blocks
}

// round 12
// speedup vs baseline: 2.0812x; 1.7716x over previous
#include <cuda_runtime.h>
#include <cuda_bf16.h>

// Problem constants (fixed by the reference)
#define WF 512.0f
#define HF 512.0f
#define NGMAX 2048
#define TILES_X 32
#define TILES_Y 32
#define TILES (TILES_X * TILES_Y)
#define TILE_W 16.0f
#define PCAP 256              // per-tile pixel capacity (mean 64, max ~110)
#define NSEG 2                // warp-segments per splat block (2 warps)
#define SEG 1024              // gaussians per segment
#define SEGCAP 160            // staged coefficients per segment (overflow -> global)
#define TPB_PREP 256
#define TPB_SPLAT 64

// Per-gaussian packed coefficients: 2 x float4: [P,Q,R,mx] [my,cr,cg,cb]
// (P,Q,R pre-scaled by -log2(e) so exp is a single ex2)
__device__ float4 g_coef[NGMAX * 2];
__device__ float4 g_cull[NGMAX];          // [mx, my, r2, 0]
__device__ int g_pcnt[TILES];             // statically zero; re-zeroed by splat
__device__ float4 g_pxyi[TILES * PCAP];   // [x, y, bitcast(pixel idx), 0]

__device__ __forceinline__ float ex2(float x) {
    float r; asm("ex2.approx.ftz.f32 %0,%1;" : "=f"(r) : "f"(x)); return r;
}
__device__ __forceinline__ float rcp(float x) {
    float r; asm("rcp.approx.ftz.f32 %0,%1;" : "=f"(r) : "f"(x)); return r;
}
__device__ __forceinline__ float fexp(float x) { return ex2(x * 1.4426950408889634f); }
__device__ __forceinline__ float ftanh(float x) {
    float e = ex2(x * 2.8853900817779268f);   // e^{2x}
    return 1.0f - 2.0f * rcp(e + 1.0f);
}
__device__ __forceinline__ float fsigm(float x) {
    return rcp(1.0f + fexp(-x));
}

// ---------------------------------------------------------------------------
// Kernel 1: coefficients (gtid < N) + pixel binning (1 px/thread).
// Cull: |d|^2 >= min(S0,S1)^2 |v|^2  =>  |v| > 4/minS gives w < e^-16;
// worst-case dropped mass <= 2048 * 1.1e-7 ~ 2e-4 absolute (budget 1e-3).
// ---------------------------------------------------------------------------
__global__ void __launch_bounds__(TPB_PREP) prep_kernel(const float* __restrict__ rgb,
                                                        const float* __restrict__ mu,
                                                        const float* __restrict__ scale,
                                                        const float* __restrict__ angle,
                                                        const float* __restrict__ x,
                                                        int N, int B) {
    int gtid = blockIdx.x * TPB_PREP + threadIdx.x;

    if (gtid < N) {
        const float MU_BORDER = 1.05f;
        const float PI_APPROX = 3.1416f;
        const float S_MIN = 1.0f / 30.0f;
        const float S_MAX = 1.0f / 0.75f;
        const float LOG2E = 1.4426950408889634f;
        int i = gtid;

        float mpx = (ftanh(mu[2 * i + 0]) * MU_BORDER + 1.0f) * 0.5f * WF;
        float mpy = (ftanh(mu[2 * i + 1]) * MU_BORDER + 1.0f) * 0.5f * HF;

        float al = ftanh(angle[i]) * PI_APPROX;
        float c, s;
        __sincosf(al, &s, &c);

        float S0 = fsigm(scale[2 * i + 0]) * (S_MAX - S_MIN) + S_MIN;
        float S1 = fsigm(scale[2 * i + 1]) * (S_MAX - S_MIN) + S_MIN;

        float a = S0 * c, b = -S0 * s;
        float e = S1 * s, f = S1 * c;

        float P = -LOG2E * (a * a + e * e);
        float Q = -LOG2E * 2.0f * (a * b + e * f);
        float R = -LOG2E * (b * b + f * f);

        float cr = fsigm(rgb[3 * i + 0]);
        float cg = fsigm(rgb[3 * i + 1]);
        float cb = fsigm(rgb[3 * i + 2]);

        float Smin = fminf(S0, S1);
        float r = 4.0f / Smin;                  // w = e^-16 level set
        float r2 = r * r * 1.0001f + 1e-2f;

        g_coef[2 * i]     = make_float4(P, Q, R, mpx);
        g_coef[2 * i + 1] = make_float4(mpy, cr, cg, cb);
        g_cull[i]         = make_float4(mpx, mpy, r2, 0.0f);
    }

    // pixel binning: 1 pixel per thread; single 16B record per pixel
    if (gtid < B) {
        float2 xy = ((const float2*)x)[gtid];
        int tx = (int)(xy.x * (1.0f / TILE_W));
        int ty = (int)(xy.y * (1.0f / TILE_W));
        tx = min(max(tx, 0), TILES_X - 1);
        ty = min(max(ty, 0), TILES_Y - 1);
        int t = ty * TILES_X + tx;
        int slot = atomicAdd(&g_pcnt[t], 1);
        if (slot < PCAP) {
            g_pxyi[t * PCAP + slot] =
                make_float4(xy.x, xy.y, __int_as_float(gtid), 0.0f);
        }
    }
}

// ---------------------------------------------------------------------------
// Kernel 2: per-tile splat, 1024 blocks x 64 threads (all co-resident).
// Warp w ballot-compacts gaussians [w*1024,(w+1)*1024) in index order,
// staging their coefficients into smem (MLP-8 batched cull loads). Pixel
// loop: ~1 px/thread over staged lists, segments 0..1 in order
// (fixed accumulation order -> deterministic). First pixel record is
// prefetched before the scan to overlap latency. Re-zeroes g_pcnt[t].
// ---------------------------------------------------------------------------
__global__ void __launch_bounds__(TPB_SPLAT) splat_tiled(float* __restrict__ out) {
    __shared__ float4 scoef[NSEG][SEGCAP][2];     // 10 KB
    __shared__ unsigned short slist[NSEG][SEG];   // 4 KB (overflow path)
    __shared__ int scnt[NSEG];

    const int t = blockIdx.x;
    const int tid = threadIdx.x;
    const int w = tid >> 5;
    const int lane = tid & 31;

    // early loads (overlap with the scan below)
    const int pcnt = min(g_pcnt[t], PCAP);
    float4 px0 = make_float4(0.f, 0.f, 0.f, 0.f);
    if (tid < pcnt) px0 = g_pxyi[t * PCAP + tid];

    const float tx0 = (float)(t & (TILES_X - 1)) * TILE_W;
    const float ty0 = (float)(t >> 5) * TILE_W;
    const float tx1 = tx0 + TILE_W;
    const float ty1 = ty0 + TILE_W;

    // ---- cull scan: warp w covers [w*SEG, (w+1)*SEG), MLP-8 batches ----
    {
        int cnt = 0;
        for (int c0 = w * SEG; c0 < (w + 1) * SEG; c0 += 256) {
            float4 cu[8];
#pragma unroll
            for (int c = 0; c < 8; c++)
                cu[c] = g_cull[c0 + c * 32 + lane];   // 8 independent LDG.128
#pragma unroll
            for (int c = 0; c < 8; c++) {
                int gi = c0 + c * 32 + lane;
                float dx = fmaxf(fmaxf(tx0 - cu[c].x, cu[c].x - tx1), 0.0f);
                float dy = fmaxf(fmaxf(ty0 - cu[c].y, cu[c].y - ty1), 0.0f);
                bool ok = (dx * dx + dy * dy) <= cu[c].z;
                unsigned m = __ballot_sync(0xffffffffu, ok);
                if (ok) {
                    int pos = cnt + __popc(m & ((1u << lane) - 1u));
                    slist[w][pos] = (unsigned short)gi;
                    if (pos < SEGCAP) {
                        scoef[w][pos][0] = g_coef[2 * gi];
                        scoef[w][pos][1] = g_coef[2 * gi + 1];
                    }
                }
                cnt += __popc(m);
            }
        }
        if (lane == 0) scnt[w] = cnt;
    }
    __syncthreads();
    if (tid == 0) g_pcnt[t] = 0;        // reset for next replay (all reads done)

    // ---- pixel loop (mean 64 px/tile -> usually one iteration) ----
    for (int i = tid; i < pcnt; i += TPB_SPLAT) {
        float4 rec = (i == tid) ? px0 : g_pxyi[t * PCAP + i];
        float px = rec.x, py = rec.y;

        float ar = 0.f, ag = 0.f, ab = 0.f;

#pragma unroll
        for (int seg = 0; seg < NSEG; seg++) {
            int n = scnt[seg];
            int nc = min(n, SEGCAP);
#pragma unroll 4
            for (int j = 0; j < nc; j++) {
                float4 cA = scoef[seg][j][0];     // P,Q,R,mx
                float4 cB = scoef[seg][j][1];     // my,cr,cg,cb
                float vx = px - cA.w;
                float vy = py - cB.x;
                float q = fmaf(vx, fmaf(cA.y, vy, cA.x * vx), (cA.z * vy) * vy);
                float wgt = ex2(q);
                ar = fmaf(wgt, cB.y, ar);
                ag = fmaf(wgt, cB.z, ag);
                ab = fmaf(wgt, cB.w, ab);
            }
            // overflow path (statistically never; preserves correctness)
            for (int j = SEGCAP; j < n; j++) {
                int gi = slist[seg][j];
                float4 cA = g_coef[2 * gi];
                float4 cB = g_coef[2 * gi + 1];
                float vx = px - cA.w;
                float vy = py - cB.x;
                float q = fmaf(vx, fmaf(cA.y, vy, cA.x * vx), (cA.z * vy) * vy);
                float wgt = ex2(q);
                ar = fmaf(wgt, cB.y, ar);
                ag = fmaf(wgt, cB.z, ag);
                ab = fmaf(wgt, cB.w, ab);
            }
        }

        int pix = __float_as_int(rec.z);
        out[3 * pix + 0] = ar;
        out[3 * pix + 1] = ag;
        out[3 * pix + 2] = ab;
    }
}

// ---------------------------------------------------------------------------
// Launch: inputs in metadata order: x[B,2], rgb[N,3], mu[N,2], scale[N,2], angle[N]
// ---------------------------------------------------------------------------
extern "C" void kernel_launch(void* const* d_in, const int* in_sizes, int n_in,
                              void* d_out, int out_size) {
    const float* x     = (const float*)d_in[0];
    const float* rgb   = (const float*)d_in[1];
    const float* mu    = (const float*)d_in[2];
    const float* scale = (const float*)d_in[3];
    const float* angle = (const float*)d_in[4];
    float* out = (float*)d_out;

    int N = in_sizes[4];          // 2048
    int B = in_sizes[0] / 2;      // 65536

    prep_kernel<<<B / TPB_PREP, TPB_PREP>>>(rgb, mu, scale, angle, x, N, B);
    splat_tiled<<<TILES, TPB_SPLAT>>>(out);
}

// round 13
// speedup vs baseline: 2.3384x; 1.1236x over previous
#include <cuda_runtime.h>
#include <cuda_bf16.h>
#include <cuda_fp16.h>

// Problem constants (fixed by the reference)
#define WF 512.0f
#define HF 512.0f
#define NGMAX 2048
#define TILES_X 32
#define TILES_Y 32
#define TILES (TILES_X * TILES_Y)
#define TILE_W 16.0f
#define PCAP 256              // per-tile pixel capacity (mean 64, max ~110)
#define NSEG 4                // warp-segments per splat block (4 warps)
#define SEG 512               // gaussians per segment
#define SEGCAP 96             // staged coefficients per segment (overflow -> global)
#define TPB_PREP 256
#define TPB_SPLAT 128

// Per-gaussian packed coefficients: 2 x float4: [P,Q,R,mx] [my,cr,cg,cb]
// (P,Q,R pre-scaled by -log2(e) so exp is a single ex2)
__device__ float4 g_coef[NGMAX * 2];
// Compact cull data: half2 center (<=0.25px rounding, folded into radius
// margin) + fp32 squared radius. 8 B/gaussian total.
__device__ __half2 g_cxy[NGMAX];
__device__ float g_cr2[NGMAX];
__device__ int g_pcnt[TILES];             // statically zero; re-zeroed by splat
__device__ float4 g_pxyi[TILES * PCAP];   // [x, y, bitcast(pixel idx), 0]

__device__ __forceinline__ float ex2(float x) {
    float r; asm("ex2.approx.ftz.f32 %0,%1;" : "=f"(r) : "f"(x)); return r;
}
__device__ __forceinline__ float rcp(float x) {
    float r; asm("rcp.approx.ftz.f32 %0,%1;" : "=f"(r) : "f"(x)); return r;
}
__device__ __forceinline__ float fexp(float x) { return ex2(x * 1.4426950408889634f); }
__device__ __forceinline__ float ftanh(float x) {
    float e = ex2(x * 2.8853900817779268f);   // e^{2x}
    return 1.0f - 2.0f * rcp(e + 1.0f);
}
__device__ __forceinline__ float fsigm(float x) {
    return rcp(1.0f + fexp(-x));
}

// ---------------------------------------------------------------------------
// Kernel 1: coefficients (gtid < N) + pixel binning (1 px/thread).
// Cull: |v| > 4/minS gives w < e^-16; dropped mass <= 2048*1.1e-7 ~ 2e-4 abs.
// Radius margin +0.36 px covers the half2 center rounding (0.25*sqrt2).
// ---------------------------------------------------------------------------
__global__ void __launch_bounds__(TPB_PREP) prep_kernel(const float* __restrict__ rgb,
                                                        const float* __restrict__ mu,
                                                        const float* __restrict__ scale,
                                                        const float* __restrict__ angle,
                                                        const float* __restrict__ x,
                                                        int N, int B) {
    int gtid = blockIdx.x * TPB_PREP + threadIdx.x;

    if (gtid < N) {
        const float MU_BORDER = 1.05f;
        const float PI_APPROX = 3.1416f;
        const float S_MIN = 1.0f / 30.0f;
        const float S_MAX = 1.0f / 0.75f;
        const float LOG2E = 1.4426950408889634f;
        int i = gtid;

        float mpx = (ftanh(mu[2 * i + 0]) * MU_BORDER + 1.0f) * 0.5f * WF;
        float mpy = (ftanh(mu[2 * i + 1]) * MU_BORDER + 1.0f) * 0.5f * HF;

        float al = ftanh(angle[i]) * PI_APPROX;
        float c, s;
        __sincosf(al, &s, &c);

        float S0 = fsigm(scale[2 * i + 0]) * (S_MAX - S_MIN) + S_MIN;
        float S1 = fsigm(scale[2 * i + 1]) * (S_MAX - S_MIN) + S_MIN;

        float a = S0 * c, b = -S0 * s;
        float e = S1 * s, f = S1 * c;

        float P = -LOG2E * (a * a + e * e);
        float Q = -LOG2E * 2.0f * (a * b + e * f);
        float R = -LOG2E * (b * b + f * f);

        float cr = fsigm(rgb[3 * i + 0]);
        float cg = fsigm(rgb[3 * i + 1]);
        float cb = fsigm(rgb[3 * i + 2]);

        float Smin = fminf(S0, S1);
        float r = 4.0f / Smin + 0.36f;          // e^-16 level set + half2 margin
        float r2 = r * r * 1.0001f + 1e-2f;

        g_coef[2 * i]     = make_float4(P, Q, R, mpx);
        g_coef[2 * i + 1] = make_float4(mpy, cr, cg, cb);
        g_cxy[i]          = __floats2half2_rn(mpx, mpy);
        g_cr2[i]          = r2;
    }

    // pixel binning: 1 pixel per thread; single 16B record per pixel
    if (gtid < B) {
        float2 xy = ((const float2*)x)[gtid];
        int tx = (int)(xy.x * (1.0f / TILE_W));
        int ty = (int)(xy.y * (1.0f / TILE_W));
        tx = min(max(tx, 0), TILES_X - 1);
        ty = min(max(ty, 0), TILES_Y - 1);
        int t = ty * TILES_X + tx;
        int slot = atomicAdd(&g_pcnt[t], 1);
        if (slot < PCAP) {
            g_pxyi[t * PCAP + slot] =
                make_float4(xy.x, xy.y, __int_as_float(gtid), 0.0f);
        }
    }
}

// ---------------------------------------------------------------------------
// Kernel 2: per-tile splat, 1024 blocks x 128 threads.
// Pass 1 (scan): warp w ballot-compacts gaussians [w*512,(w+1)*512) in index
//   order into slist (indices only; 2 MLP-8 batches of 8B cull records).
// Pass 2 (stage): all 128 threads cooperatively gather the hit coefficients
//   into smem at full MLP (one latency exposure).
// Pass 3 (splat): ~1 px/thread over staged lists, segments 0..3 in order
//   (fixed accumulation order -> deterministic). Re-zeroes g_pcnt[t].
// ---------------------------------------------------------------------------
__global__ void __launch_bounds__(TPB_SPLAT) splat_tiled(float* __restrict__ out) {
    __shared__ float4 scoef[NSEG][SEGCAP][2];     // 12 KB
    __shared__ unsigned short slist[NSEG][SEG];   // 4 KB
    __shared__ int scnt[NSEG];

    const int t = blockIdx.x;
    const int tid = threadIdx.x;
    const int w = tid >> 5;
    const int lane = tid & 31;

    // early loads (overlap with the scan below)
    const int pcnt = min(g_pcnt[t], PCAP);
    float4 px0 = make_float4(0.f, 0.f, 0.f, 0.f);
    if (tid < pcnt) px0 = g_pxyi[t * PCAP + tid];

    const float tx0 = (float)(t & (TILES_X - 1)) * TILE_W;
    const float ty0 = (float)(t >> 5) * TILE_W;
    const float tx1 = tx0 + TILE_W;
    const float ty1 = ty0 + TILE_W;

    // ---- Pass 1: cull scan, warp w covers [w*SEG,(w+1)*SEG), MLP-8 ----
    {
        int cnt = 0;
#pragma unroll
        for (int b = 0; b < SEG / 256; b++) {        // 2 batches of 8 chunks
            int c0 = w * SEG + b * 256;
            __half2 cxy[8];
            float cr2[8];
#pragma unroll
            for (int c = 0; c < 8; c++) {            // 16 independent LDG.32
                cxy[c] = g_cxy[c0 + c * 32 + lane];
                cr2[c] = g_cr2[c0 + c * 32 + lane];
            }
#pragma unroll
            for (int c = 0; c < 8; c++) {
                float2 m = __half22float2(cxy[c]);
                float dx = fmaxf(fmaxf(tx0 - m.x, m.x - tx1), 0.0f);
                float dy = fmaxf(fmaxf(ty0 - m.y, m.y - ty1), 0.0f);
                bool ok = (dx * dx + dy * dy) <= cr2[c];
                unsigned msk = __ballot_sync(0xffffffffu, ok);
                if (ok) {
                    int pos = cnt + __popc(msk & ((1u << lane) - 1u));
                    slist[w][pos] = (unsigned short)(c0 + c * 32 + lane);
                }
                cnt += __popc(msk);
            }
        }
        if (lane == 0) scnt[w] = cnt;
    }
    __syncthreads();
    if (tid == 0) g_pcnt[t] = 0;          // reset for next graph replay

    // ---- Pass 2: cooperative coefficient staging (full-MLP gather) ----
#pragma unroll
    for (int seg = 0; seg < NSEG; seg++) {
        int nc = min(scnt[seg], SEGCAP);
        for (int j = tid; j < nc; j += TPB_SPLAT) {
            int gi = slist[seg][j];
            scoef[seg][j][0] = g_coef[2 * gi];
            scoef[seg][j][1] = g_coef[2 * gi + 1];
        }
    }
    __syncthreads();

    // ---- Pass 3: pixel loop (mean 64 px/tile -> one iteration) ----
    for (int i = tid; i < pcnt; i += TPB_SPLAT) {
        float4 rec = (i == tid) ? px0 : g_pxyi[t * PCAP + i];
        float px = rec.x, py = rec.y;

        float ar = 0.f, ag = 0.f, ab = 0.f;

#pragma unroll
        for (int seg = 0; seg < NSEG; seg++) {
            int n = scnt[seg];
            int nc = min(n, SEGCAP);
#pragma unroll 4
            for (int j = 0; j < nc; j++) {
                float4 cA = scoef[seg][j][0];     // P,Q,R,mx
                float4 cB = scoef[seg][j][1];     // my,cr,cg,cb
                float vx = px - cA.w;
                float vy = py - cB.x;
                float q = fmaf(vx, fmaf(cA.y, vy, cA.x * vx), (cA.z * vy) * vy);
                float wgt = ex2(q);
                ar = fmaf(wgt, cB.y, ar);
                ag = fmaf(wgt, cB.z, ag);
                ab = fmaf(wgt, cB.w, ab);
            }
            // overflow path (statistically never; preserves correctness)
            for (int j = SEGCAP; j < n; j++) {
                int gi = slist[seg][j];
                float4 cA = g_coef[2 * gi];
                float4 cB = g_coef[2 * gi + 1];
                float vx = px - cA.w;
                float vy = py - cB.x;
                float q = fmaf(vx, fmaf(cA.y, vy, cA.x * vx), (cA.z * vy) * vy);
                float wgt = ex2(q);
                ar = fmaf(wgt, cB.y, ar);
                ag = fmaf(wgt, cB.z, ag);
                ab = fmaf(wgt, cB.w, ab);
            }
        }

        int pix = __float_as_int(rec.z);
        out[3 * pix + 0] = ar;
        out[3 * pix + 1] = ag;
        out[3 * pix + 2] = ab;
    }
}

// ---------------------------------------------------------------------------
// Launch: inputs in metadata order: x[B,2], rgb[N,3], mu[N,2], scale[N,2], angle[N]
// ---------------------------------------------------------------------------
extern "C" void kernel_launch(void* const* d_in, const int* in_sizes, int n_in,
                              void* d_out, int out_size) {
    const float* x     = (const float*)d_in[0];
    const float* rgb   = (const float*)d_in[1];
    const float* mu    = (const float*)d_in[2];
    const float* scale = (const float*)d_in[3];
    const float* angle = (const float*)d_in[4];
    float* out = (float*)d_out;

    int N = in_sizes[4];          // 2048
    int B = in_sizes[0] / 2;      // 65536

    prep_kernel<<<B / TPB_PREP, TPB_PREP>>>(rgb, mu, scale, angle, x, N, B);
    splat_tiled<<<TILES, TPB_SPLAT>>>(out);
}

// round 14
// speedup vs baseline: 2.6115x; 1.1168x over previous
#include <cuda_runtime.h>
#include <cuda_bf16.h>

// Problem constants (fixed by the reference)
#define WF 512.0f
#define HF 512.0f
#define NGMAX 2048
#define TILES_X 32
#define TILES_Y 32
#define TILES (TILES_X * TILES_Y)
#define TILE_W 16.0f
#define PCAP 256              // per-tile pixel capacity (mean 64, max ~110)
#define MWORDS 64             // 2048 bits per tile mask
#define SCAP 320              // staged coefficients (observed max ~<320)
#define TPB_PREP 256
#define TPB_SPLAT 64

// Per-gaussian packed coefficients: 2 x float4: [P,Q,R,mx] [my,cr,cg,cb]
// (P,Q,R pre-scaled by -log2(e) so exp is a single ex2)
__device__ float4 g_coef[NGMAX * 2];
// Per-tile gaussian bitmask (2048 bits). atomicOr is commutative+idempotent
// -> deterministic. Statically zero; splat re-zeroes after reading.
__device__ unsigned g_gmask[TILES * MWORDS];
__device__ int g_pcnt[TILES];             // statically zero; re-zeroed by splat
__device__ float4 g_pxyi[TILES * PCAP];   // [x, y, bitcast(pixel idx), 0]

__device__ __forceinline__ float ex2(float x) {
    float r; asm("ex2.approx.ftz.f32 %0,%1;" : "=f"(r) : "f"(x)); return r;
}
__device__ __forceinline__ float rcp(float x) {
    float r; asm("rcp.approx.ftz.f32 %0,%1;" : "=f"(r) : "f"(x)); return r;
}
__device__ __forceinline__ float fexp(float x) { return ex2(x * 1.4426950408889634f); }
__device__ __forceinline__ float ftanh(float x) {
    float e = ex2(x * 2.8853900817779268f);   // e^{2x}
    return 1.0f - 2.0f * rcp(e + 1.0f);
}
__device__ __forceinline__ float fsigm(float x) {
    return rcp(1.0f + fexp(-x));
}

// ---------------------------------------------------------------------------
// Kernel 1: per-gaussian coefficients + gaussian->tile bitmask binning
// (gtid < N), and pixel->tile binning (1 px/thread, all threads).
// Cull: |v| > 4/minS gives w < e^-16; dropped mass <= 2048*1.1e-7 ~ 2e-4 abs.
// ---------------------------------------------------------------------------
__global__ void __launch_bounds__(TPB_PREP) prep_kernel(const float* __restrict__ rgb,
                                                        const float* __restrict__ mu,
                                                        const float* __restrict__ scale,
                                                        const float* __restrict__ angle,
                                                        const float* __restrict__ x,
                                                        int N, int B) {
    int gtid = blockIdx.x * TPB_PREP + threadIdx.x;

    if (gtid < N) {
        const float MU_BORDER = 1.05f;
        const float PI_APPROX = 3.1416f;
        const float S_MIN = 1.0f / 30.0f;
        const float S_MAX = 1.0f / 0.75f;
        const float LOG2E = 1.4426950408889634f;
        int i = gtid;

        float mpx = (ftanh(mu[2 * i + 0]) * MU_BORDER + 1.0f) * 0.5f * WF;
        float mpy = (ftanh(mu[2 * i + 1]) * MU_BORDER + 1.0f) * 0.5f * HF;

        float al = ftanh(angle[i]) * PI_APPROX;
        float c, s;
        __sincosf(al, &s, &c);

        float S0 = fsigm(scale[2 * i + 0]) * (S_MAX - S_MIN) + S_MIN;
        float S1 = fsigm(scale[2 * i + 1]) * (S_MAX - S_MIN) + S_MIN;

        float a = S0 * c, b = -S0 * s;
        float e = S1 * s, f = S1 * c;

        float P = -LOG2E * (a * a + e * e);
        float Q = -LOG2E * 2.0f * (a * b + e * f);
        float R = -LOG2E * (b * b + f * f);

        float cr = fsigm(rgb[3 * i + 0]);
        float cg = fsigm(rgb[3 * i + 1]);
        float cb = fsigm(rgb[3 * i + 2]);

        g_coef[2 * i]     = make_float4(P, Q, R, mpx);
        g_coef[2 * i + 1] = make_float4(mpy, cr, cg, cb);

        // ---- gaussian -> tile bitmask binning ----
        float Smin = fminf(S0, S1);
        float r = 4.0f / Smin;                 // w = e^-16 level set
        float r2 = r * r * 1.0001f + 1e-2f;

        int txmin = max(0, (int)((mpx - r) * (1.0f / TILE_W)));
        int txmax = min(TILES_X - 1, (int)((mpx + r) * (1.0f / TILE_W)));
        int tymin = max(0, (int)((mpy - r) * (1.0f / TILE_W)));
        int tymax = min(TILES_Y - 1, (int)((mpy + r) * (1.0f / TILE_W)));

        unsigned bit = 1u << (i & 31);
        int word = i >> 5;

        for (int ty = tymin; ty <= tymax; ty++) {
            float y0 = ty * TILE_W, y1 = y0 + TILE_W;
            float dy = fmaxf(fmaxf(y0 - mpy, mpy - y1), 0.0f);
            for (int tx = txmin; tx <= txmax; tx++) {
                float x0 = tx * TILE_W, x1 = x0 + TILE_W;
                float dx = fmaxf(fmaxf(x0 - mpx, mpx - x1), 0.0f);
                if (dx * dx + dy * dy <= r2) {
                    atomicOr(&g_gmask[(ty * TILES_X + tx) * MWORDS + word], bit);
                }
            }
        }
    }

    // pixel binning: 1 pixel per thread; single 16B record per pixel
    if (gtid < B) {
        float2 xy = ((const float2*)x)[gtid];
        int tx = (int)(xy.x * (1.0f / TILE_W));
        int ty = (int)(xy.y * (1.0f / TILE_W));
        tx = min(max(tx, 0), TILES_X - 1);
        ty = min(max(ty, 0), TILES_Y - 1);
        int t = ty * TILES_X + tx;
        int slot = atomicAdd(&g_pcnt[t], 1);
        if (slot < PCAP) {
            g_pxyi[t * PCAP + slot] =
                make_float4(xy.x, xy.y, __int_as_float(gtid), 0.0f);
        }
    }
}

// ---------------------------------------------------------------------------
// Kernel 2: per-tile splat, 1024 blocks x 64 threads.
// Thread tid reads mask word tid (1 LDG.32), re-zeroes it, popc + warp
// prefix-sum -> each word's bits expand into slist in ASCENDING INDEX ORDER
// (deterministic accumulation). Coefficients staged cooperatively, then
// ~1-2 px/thread over the staged list. Re-zeroes g_pcnt[t].
// ---------------------------------------------------------------------------
__global__ void __launch_bounds__(TPB_SPLAT) splat_tiled(float* __restrict__ out) {
    __shared__ unsigned short slist[NGMAX];   // 4 KB (full-safety capacity)
    __shared__ float4 scoef[SCAP][2];         // 10 KB
    __shared__ int wtot[2];

    const int t = blockIdx.x;
    const int tid = threadIdx.x;
    const int wid = tid >> 5;
    const int lane = tid & 31;

    // early pixel-record prefetch (overlaps the list build)
    const int pcnt = min(g_pcnt[t], PCAP);
    float4 px0 = make_float4(0.f, 0.f, 0.f, 0.f);
    if (tid < pcnt) px0 = g_pxyi[t * PCAP + tid];

    // ---- build gaussian list from the bitmask ----
    unsigned m = g_gmask[t * MWORDS + tid];
    g_gmask[t * MWORDS + tid] = 0;            // reset for next graph replay
    int c = __popc(m);
    int inc = c;
#pragma unroll
    for (int d = 1; d < 32; d <<= 1) {
        int v = __shfl_up_sync(0xffffffffu, inc, d);
        if (lane >= d) inc += v;
    }
    if (lane == 31) wtot[wid] = inc;
    __syncthreads();
    int off = inc - c + (wid ? wtot[0] : 0);  // exclusive prefix across block
    const int total = wtot[0] + wtot[1];

    {
        unsigned mm = m;
        int o = off;
        int base = tid * 32;
        while (mm) {
            int b = __ffs(mm) - 1;
            slist[o++] = (unsigned short)(base + b);
            mm &= mm - 1;
        }
    }
    __syncthreads();

    // ---- cooperative coefficient staging (full-MLP gather) ----
    const int nc = min(total, SCAP);
    for (int j = tid; j < nc; j += TPB_SPLAT) {
        int gi = slist[j];
        scoef[j][0] = g_coef[2 * gi];
        scoef[j][1] = g_coef[2 * gi + 1];
    }
    if (tid == 0) g_pcnt[t] = 0;              // reset for next graph replay
    __syncthreads();

    // ---- pixel loop (mean 64 px/tile) ----
    for (int i = tid; i < pcnt; i += TPB_SPLAT) {
        float4 rec = (i == tid) ? px0 : g_pxyi[t * PCAP + i];
        float px = rec.x, py = rec.y;

        float ar = 0.f, ag = 0.f, ab = 0.f;

#pragma unroll 4
        for (int j = 0; j < nc; j++) {
            float4 cA = scoef[j][0];          // P,Q,R,mx
            float4 cB = scoef[j][1];          // my,cr,cg,cb
            float vx = px - cA.w;
            float vy = py - cB.x;
            float q = fmaf(vx, fmaf(cA.y, vy, cA.x * vx), (cA.z * vy) * vy);
            float wgt = ex2(q);
            ar = fmaf(wgt, cB.y, ar);
            ag = fmaf(wgt, cB.z, ag);
            ab = fmaf(wgt, cB.w, ab);
        }
        // overflow path (statistically never; preserves correctness)
        for (int j = SCAP; j < total; j++) {
            int gi = slist[j];
            float4 cA = g_coef[2 * gi];
            float4 cB = g_coef[2 * gi + 1];
            float vx = px - cA.w;
            float vy = py - cB.x;
            float q = fmaf(vx, fmaf(cA.y, vy, cA.x * vx), (cA.z * vy) * vy);
            float wgt = ex2(q);
            ar = fmaf(wgt, cB.y, ar);
            ag = fmaf(wgt, cB.z, ag);
            ab = fmaf(wgt, cB.w, ab);
        }

        int pix = __float_as_int(rec.z);
        out[3 * pix + 0] = ar;
        out[3 * pix + 1] = ag;
        out[3 * pix + 2] = ab;
    }
}

// ---------------------------------------------------------------------------
// Launch: inputs in metadata order: x[B,2], rgb[N,3], mu[N,2], scale[N,2], angle[N]
// ---------------------------------------------------------------------------
extern "C" void kernel_launch(void* const* d_in, const int* in_sizes, int n_in,
                              void* d_out, int out_size) {
    const float* x     = (const float*)d_in[0];
    const float* rgb   = (const float*)d_in[1];
    const float* mu    = (const float*)d_in[2];
    const float* scale = (const float*)d_in[3];
    const float* angle = (const float*)d_in[4];
    float* out = (float*)d_out;

    int N = in_sizes[4];          // 2048
    int B = in_sizes[0] / 2;      // 65536

    prep_kernel<<<B / TPB_PREP, TPB_PREP>>>(rgb, mu, scale, angle, x, N, B);
    splat_tiled<<<TILES, TPB_SPLAT>>>(out);
}

// round 15
// speedup vs baseline: 2.6509x; 1.0151x over previous
#include <cuda_runtime.h>
#include <cuda_bf16.h>

// Problem constants (fixed by the reference)
#define WF 512.0f
#define HF 512.0f
#define NGMAX 2048
#define TILES_X 32
#define TILES_Y 32
#define TILES (TILES_X * TILES_Y)
#define TILE_W 16.0f
#define PCAP 256              // per-tile pixel capacity (mean 64, max ~110)
#define MWORDS 64             // 2048 bits per tile mask
#define SCAP 320              // staged coefficients (observed max well below)
#define TPB_PREP 256
#define TPB_SPLAT 128

// Per-gaussian packed coefficients: 2 x float4: [P,Q,R,mx] [my,cr,cg,cb]
// (P,Q,R pre-scaled by -log2(e) so exp is a single ex2)
__device__ float4 g_coef[NGMAX * 2];
// Per-tile gaussian bitmask (2048 bits). atomicOr is commutative+idempotent
// -> deterministic. Statically zero; splat re-zeroes after reading.
__device__ unsigned g_gmask[TILES * MWORDS];
__device__ int g_pcnt[TILES];             // statically zero; re-zeroed by splat
__device__ float4 g_pxyi[TILES * PCAP];   // [x, y, bitcast(pixel idx), 0]

__device__ __forceinline__ float ex2(float x) {
    float r; asm("ex2.approx.ftz.f32 %0,%1;" : "=f"(r) : "f"(x)); return r;
}
__device__ __forceinline__ float rcp(float x) {
    float r; asm("rcp.approx.ftz.f32 %0,%1;" : "=f"(r) : "f"(x)); return r;
}
__device__ __forceinline__ float fexp(float x) { return ex2(x * 1.4426950408889634f); }
__device__ __forceinline__ float ftanh(float x) {
    float e = ex2(x * 2.8853900817779268f);   // e^{2x}
    return 1.0f - 2.0f * rcp(e + 1.0f);
}
__device__ __forceinline__ float fsigm(float x) {
    return rcp(1.0f + fexp(-x));
}

// ---------------------------------------------------------------------------
// Kernel 1: warp w owns gaussian w. All 32 lanes redundantly compute the
// gaussian's coefficients from warp-uniform loads (no extra latency; they
// would otherwise idle); lane 0 writes them. The tile-box circle test is
// LANE-PARALLEL (up to 32 tiles per round) -> kills the big-gaussian
// straggler (worst box ~225 tiles = 8 rounds instead of 225 serial).
// Every thread also bins exactly 1 pixel.
// Cull: |v| > 4/minS gives w < e^-16; dropped mass <= 2048*1.1e-7 ~ 2e-4 abs.
// ---------------------------------------------------------------------------
__global__ void __launch_bounds__(TPB_PREP) prep_kernel(const float* __restrict__ rgb,
                                                        const float* __restrict__ mu,
                                                        const float* __restrict__ scale,
                                                        const float* __restrict__ angle,
                                                        const float* __restrict__ x,
                                                        int N, int B) {
    int gtid = blockIdx.x * TPB_PREP + threadIdx.x;
    int gi   = gtid >> 5;          // gaussian owned by this warp (65536/32 = 2048)
    int lane = gtid & 31;

    // pixel-binning load issued FIRST (independent of everything below)
    float2 xy = make_float2(0.f, 0.f);
    if (gtid < B) xy = ((const float2*)x)[gtid];

    if (gi < N) {
        const float MU_BORDER = 1.05f;
        const float PI_APPROX = 3.1416f;
        const float S_MIN = 1.0f / 30.0f;
        const float S_MAX = 1.0f / 0.75f;
        const float LOG2E = 1.4426950408889634f;

        // warp-uniform loads (broadcast), redundantly computed by all lanes
        float mpx = (ftanh(mu[2 * gi + 0]) * MU_BORDER + 1.0f) * 0.5f * WF;
        float mpy = (ftanh(mu[2 * gi + 1]) * MU_BORDER + 1.0f) * 0.5f * HF;

        float al = ftanh(angle[gi]) * PI_APPROX;
        float c, s;
        __sincosf(al, &s, &c);

        float S0 = fsigm(scale[2 * gi + 0]) * (S_MAX - S_MIN) + S_MIN;
        float S1 = fsigm(scale[2 * gi + 1]) * (S_MAX - S_MIN) + S_MIN;

        float a = S0 * c, b = -S0 * s;
        float e = S1 * s, f = S1 * c;

        float P = -LOG2E * (a * a + e * e);
        float Q = -LOG2E * 2.0f * (a * b + e * f);
        float R = -LOG2E * (b * b + f * f);

        if (lane == 0) {
            float cr = fsigm(rgb[3 * gi + 0]);
            float cg = fsigm(rgb[3 * gi + 1]);
            float cb = fsigm(rgb[3 * gi + 2]);
            g_coef[2 * gi]     = make_float4(P, Q, R, mpx);
            g_coef[2 * gi + 1] = make_float4(mpy, cr, cg, cb);
        }

        // ---- lane-parallel gaussian -> tile bitmask binning ----
        float Smin = fminf(S0, S1);
        float r = 4.0f / Smin;                 // w = e^-16 level set
        float r2 = r * r * 1.0001f + 1e-2f;

        int txmin = max(0, (int)((mpx - r) * (1.0f / TILE_W)));
        int txmax = min(TILES_X - 1, (int)((mpx + r) * (1.0f / TILE_W)));
        int tymin = max(0, (int)((mpy - r) * (1.0f / TILE_W)));
        int tymax = min(TILES_Y - 1, (int)((mpy + r) * (1.0f / TILE_W)));
        int bw = txmax - txmin + 1;
        int bh = tymax - tymin + 1;
        int nbox = bw * bh;

        unsigned bit = 1u << (gi & 31);
        int word = gi >> 5;

        for (int idx = lane; idx < nbox; idx += 32) {
            int ty = tymin + idx / bw;
            int tx = txmin + idx - (idx / bw) * bw;
            float x0 = tx * TILE_W, x1 = x0 + TILE_W;
            float y0 = ty * TILE_W, y1 = y0 + TILE_W;
            float dx = fmaxf(fmaxf(x0 - mpx, mpx - x1), 0.0f);
            float dy = fmaxf(fmaxf(y0 - mpy, mpy - y1), 0.0f);
            if (dx * dx + dy * dy <= r2) {
                atomicOr(&g_gmask[(ty * TILES_X + tx) * MWORDS + word], bit);
            }
        }
    }

    // ---- pixel binning: 1 pixel per thread; single 16B record ----
    if (gtid < B) {
        int tx = (int)(xy.x * (1.0f / TILE_W));
        int ty = (int)(xy.y * (1.0f / TILE_W));
        tx = min(max(tx, 0), TILES_X - 1);
        ty = min(max(ty, 0), TILES_Y - 1);
        int t = ty * TILES_X + tx;
        int slot = atomicAdd(&g_pcnt[t], 1);
        if (slot < PCAP) {
            g_pxyi[t * PCAP + slot] =
                make_float4(xy.x, xy.y, __int_as_float(gtid), 0.0f);
        }
    }
}

// ---------------------------------------------------------------------------
// Kernel 2: per-tile splat, 1024 blocks x 128 threads (4 warps for latency
// cover). All independent loads (pcnt, pixel record, mask word) issue at the
// top. Threads 0-63 expand the bitmask into an ASCENDING-INDEX list
// (2-warp prefix sum; deterministic order), all 128 gather coefficients,
// then pcnt<=~110 pixels run fully parallel (usually one iteration).
// Re-zeroes g_gmask and g_pcnt for the next graph replay.
// ---------------------------------------------------------------------------
__global__ void __launch_bounds__(TPB_SPLAT) splat_tiled(float* __restrict__ out) {
    __shared__ unsigned short slist[NGMAX];   // 4 KB (full-safety capacity)
    __shared__ float4 scoef[SCAP][2];         // 10 KB
    __shared__ int wtot[2];

    const int t = blockIdx.x;
    const int tid = threadIdx.x;
    const int wid = tid >> 5;
    const int lane = tid & 31;

    // ---- independent top-of-kernel loads (max MLP) ----
    const int pcnt = min(g_pcnt[t], PCAP);
    float4 px0 = make_float4(0.f, 0.f, 0.f, 0.f);
    if (tid < pcnt) px0 = g_pxyi[t * PCAP + tid];
    unsigned m = 0;
    if (tid < MWORDS) {
        m = g_gmask[t * MWORDS + tid];
        g_gmask[t * MWORDS + tid] = 0;        // reset for next graph replay
    }

    // ---- build gaussian list (threads 0-63; ascending index order) ----
    int c = __popc(m);
    int inc = c;
#pragma unroll
    for (int d = 1; d < 32; d <<= 1) {
        int v = __shfl_up_sync(0xffffffffu, inc, d);
        if (lane >= d) inc += v;
    }
    if (wid < 2 && lane == 31) wtot[wid] = inc;
    __syncthreads();
    const int total = wtot[0] + wtot[1];

    if (tid < MWORDS) {
        int off = inc - c + (wid ? wtot[0] : 0);
        unsigned mm = m;
        int o = off;
        int base = tid * 32;
        while (mm) {
            int b = __ffs(mm) - 1;
            slist[o++] = (unsigned short)(base + b);
            mm &= mm - 1;
        }
    }
    __syncthreads();

    // ---- cooperative coefficient staging (full-MLP gather) ----
    const int nc = min(total, SCAP);
    for (int j = tid; j < nc; j += TPB_SPLAT) {
        int gi = slist[j];
        scoef[j][0] = g_coef[2 * gi];
        scoef[j][1] = g_coef[2 * gi + 1];
    }
    if (tid == 0) g_pcnt[t] = 0;              // reset for next graph replay
    __syncthreads();

    // ---- pixel loop: pcnt <= ~110 < 128 -> normally ONE iteration ----
    for (int i = tid; i < pcnt; i += TPB_SPLAT) {
        float4 rec = (i == tid) ? px0 : g_pxyi[t * PCAP + i];
        float px = rec.x, py = rec.y;

        float ar = 0.f, ag = 0.f, ab = 0.f;

#pragma unroll 4
        for (int j = 0; j < nc; j++) {
            float4 cA = scoef[j][0];          // P,Q,R,mx
            float4 cB = scoef[j][1];          // my,cr,cg,cb
            float vx = px - cA.w;
            float vy = py - cB.x;
            float q = fmaf(vx, fmaf(cA.y, vy, cA.x * vx), (cA.z * vy) * vy);
            float wgt = ex2(q);
            ar = fmaf(wgt, cB.y, ar);
            ag = fmaf(wgt, cB.z, ag);
            ab = fmaf(wgt, cB.w, ab);
        }
        // overflow path (statistically never; preserves correctness)
        for (int j = SCAP; j < total; j++) {
            int gi = slist[j];
            float4 cA = g_coef[2 * gi];
            float4 cB = g_coef[2 * gi + 1];
            float vx = px - cA.w;
            float vy = py - cB.x;
            float q = fmaf(vx, fmaf(cA.y, vy, cA.x * vx), (cA.z * vy) * vy);
            float wgt = ex2(q);
            ar = fmaf(wgt, cB.y, ar);
            ag = fmaf(wgt, cB.z, ag);
            ab = fmaf(wgt, cB.w, ab);
        }

        int pix = __float_as_int(rec.z);
        out[3 * pix + 0] = ar;
        out[3 * pix + 1] = ag;
        out[3 * pix + 2] = ab;
    }
}

// ---------------------------------------------------------------------------
// Launch: inputs in metadata order: x[B,2], rgb[N,3], mu[N,2], scale[N,2], angle[N]
// ---------------------------------------------------------------------------
extern "C" void kernel_launch(void* const* d_in, const int* in_sizes, int n_in,
                              void* d_out, int out_size) {
    const float* x     = (const float*)d_in[0];
    const float* rgb   = (const float*)d_in[1];
    const float* mu    = (const float*)d_in[2];
    const float* scale = (const float*)d_in[3];
    const float* angle = (const float*)d_in[4];
    float* out = (float*)d_out;

    int N = in_sizes[4];          // 2048
    int B = in_sizes[0] / 2;      // 65536

    prep_kernel<<<B / TPB_PREP, TPB_PREP>>>(rgb, mu, scale, angle, x, N, B);
    splat_tiled<<<TILES, TPB_SPLAT>>>(out);
}